// round 15
// baseline (speedup 1.0000x reference)
#include <cuda_runtime.h>
#include <math.h>

#define T_STEPS 32
#define NN      1024
#define H       256
#define LDIM    128
#define V       800
#define BB      256
#define NB      15
#define E       (T_STEPS * NN)   /* 32768 */
#define R       (E + BB)         /* 33024 */

// ---------------- device scratch ----------------
__device__ float g_hbuf[(E + 1) * H];
__device__ float g_Urh[(E + 1) * H];
__device__ float g_curo[(size_t)R * H];
__device__ float g_sh[NN * H];
__device__ float g_xg[NN * H];
__device__ float g_Epre[800 * 1024];   // [E_z|E_r|E_h|E_ui] per word, biases folded
__device__ float g_Xpu[BB * 512];      // [Xp|Xu] per context, biases folded
__device__ float g_Wcat[1024 * H];
__device__ float g_Wx[512 * LDIM];
__device__ float g_bcat[1024];
__device__ float g_bcat2[512];
__device__ float g_h2[(size_t)R * H];
__device__ float g_big[(size_t)R * V];
__device__ int   g_pidx[R];
__device__ int   g_pctx[R];
__device__ int   g_cnt;
__device__ float g_rowNll[R], g_rowHit[R], g_rowBce[R], g_rowSAcc[R];

// ---------------- init ----------------
__global__ void k_init() {
    int j = threadIdx.x;
    if (blockIdx.x == 0) g_hbuf[E * H + j] = 0.f;
    else                 g_Urh[E * H + j] = 0.f;
}

// ---------------- build combined weights ----------------
__global__ void k_prep(const float* __restrict__ Wz, const float* __restrict__ Wzb,
                       const float* __restrict__ Wr, const float* __restrict__ Wrb,
                       const float* __restrict__ Wh, const float* __restrict__ Whb,
                       const float* __restrict__ Ui, const float* __restrict__ Uib,
                       const float* __restrict__ Ww, const float* __restrict__ Wb,
                       const float* __restrict__ Uw, const float* __restrict__ Ub) {
    int r = blockIdx.x, j = threadIdx.x;
    if (r < 1024) {
        int rr = r & 255;
        float v, b;
        if (r < 256)      { v = Wz[rr * 512 + j]; b = Wzb[rr]; }
        else if (r < 512) { v = Wr[rr * 256 + j]; b = Wrb[rr]; }
        else if (r < 768) { v = Wh[rr * 512 + j]; b = Whb[rr]; }
        else              { v = Ui[rr * 512 + j]; b = Uib[rr]; }
        g_Wcat[r * H + j] = v;
        if (j == 0) g_bcat[r] = b;
    } else {
        int r2 = r - 1024;
        int rr = r2 & 255;
        if (j < LDIM)
            g_Wx[r2 * LDIM + j] = (r2 < 256) ? Ww[rr * 384 + 256 + j] : Uw[rr * 384 + 256 + j];
        if (j == 0) g_bcat2[r2] = (r2 < 256) ? Wb[rr] : Ub[rr];
    }
}

// ---------------- double-buffered fp32 GEMM: C = epi(A[M,K] @ W[Nc,K]^T) ---
// BM in {16, 32, 64} (TM = BM/16 in {1, 2, 4}).
// EPI: 0=plain 1=+bias 2=relu(+addMat[id])
// IM (EPI==2): 1 id=idxA[gr]; 2 id=gr<E?idxA[gr]:idxB[gr-E]; 3 id=gr<E?idxA[gr]:gr-E
// GA: A rows gathered from g_hbuf via gidx (pi<BB -> zero row)
template <int BM, int EPI, int IM, bool GA>
__global__ void __launch_bounds__(256) k_gemm(
    const float* __restrict__ A, int lda, int Mh, const int* __restrict__ Mptr,
    const float* __restrict__ W, int ldw, int Nc, int K,
    const float* __restrict__ bias,
    float* __restrict__ C, int ldc,
    const float* __restrict__ addMat, int addStride,
    const int* __restrict__ idxA, const int* __restrict__ idxB,
    const int* __restrict__ gidx) {
    const int M = Mptr ? *Mptr : Mh;
    const int bm = blockIdx.y * BM;
    if (bm >= M) return;
    const int bn = blockIdx.x * 64;
    __shared__ __align__(16) float sA[2][16][BM];
    __shared__ __align__(16) float sW[2][16][64];
    const int tid = threadIdx.x;
    constexpr int TM = BM / 16;
    const int tx = tid & 15, ty = tid >> 4;
    float acc[TM][4];
#pragma unroll
    for (int i = 0; i < TM; i++)
#pragma unroll
        for (int j = 0; j < 4; j++) acc[i][j] = 0.f;
    const int lr = tid >> 2, lk = (tid & 3) << 2;
    const bool wok = (bn + lr) < Nc;
    bool aok = (lr < BM) && ((bm + lr) < M);
    const float* Wp = W + (size_t)(bn + lr) * ldw + lk;
    const float* Ap = A;
    if (GA) {
        Ap = g_hbuf;
        if (aok) {
            int pi = gidx[bm + lr];
            if (pi < BB) aok = false;
            else Ap = g_hbuf + (size_t)(pi - BB) * H + lk;
        }
    } else {
        Ap = A + (size_t)(bm + (lr < BM ? lr : 0)) * lda + lk;
    }

    const int P = K / 16;
    const float4 z4 = make_float4(0.f, 0.f, 0.f, 0.f);
    float4 wR = wok ? *(const float4*)(Wp) : z4;
    float4 aR = z4;
    if (lr < BM) aR = aok ? *(const float4*)(Ap) : z4;
    sW[0][lk + 0][lr] = wR.x; sW[0][lk + 1][lr] = wR.y;
    sW[0][lk + 2][lr] = wR.z; sW[0][lk + 3][lr] = wR.w;
    if (lr < BM) {
        sA[0][lk + 0][lr] = aR.x; sA[0][lk + 1][lr] = aR.y;
        sA[0][lk + 2][lr] = aR.z; sA[0][lk + 3][lr] = aR.w;
    }
    __syncthreads();

    for (int p = 0; p < P; p++) {
        const int cb = p & 1, nb = cb ^ 1;
        if (p + 1 < P) {
            int k0 = (p + 1) * 16;
            wR = wok ? *(const float4*)(Wp + k0) : z4;
            if (lr < BM) aR = aok ? *(const float4*)(Ap + k0) : z4;
        }
#pragma unroll
        for (int k = 0; k < 16; k++) {
            float4 wv = *(const float4*)&sW[cb][k][tx * 4];
            if constexpr (TM == 4) {
                float4 av = *(const float4*)&sA[cb][k][ty * 4];
                acc[0][0] += av.x * wv.x; acc[0][1] += av.x * wv.y; acc[0][2] += av.x * wv.z; acc[0][3] += av.x * wv.w;
                acc[1][0] += av.y * wv.x; acc[1][1] += av.y * wv.y; acc[1][2] += av.y * wv.z; acc[1][3] += av.y * wv.w;
                acc[2][0] += av.z * wv.x; acc[2][1] += av.z * wv.y; acc[2][2] += av.z * wv.z; acc[2][3] += av.z * wv.w;
                acc[3][0] += av.w * wv.x; acc[3][1] += av.w * wv.y; acc[3][2] += av.w * wv.z; acc[3][3] += av.w * wv.w;
            } else if constexpr (TM == 2) {
                float2 av = *(const float2*)&sA[cb][k][ty * 2];
                acc[0][0] += av.x * wv.x; acc[0][1] += av.x * wv.y; acc[0][2] += av.x * wv.z; acc[0][3] += av.x * wv.w;
                acc[1][0] += av.y * wv.x; acc[1][1] += av.y * wv.y; acc[1][2] += av.y * wv.z; acc[1][3] += av.y * wv.w;
            } else {   // TM == 1
                float av = sA[cb][k][ty];
                acc[0][0] += av * wv.x; acc[0][1] += av * wv.y;
                acc[0][2] += av * wv.z; acc[0][3] += av * wv.w;
            }
        }
        if (p + 1 < P) {
            sW[nb][lk + 0][lr] = wR.x; sW[nb][lk + 1][lr] = wR.y;
            sW[nb][lk + 2][lr] = wR.z; sW[nb][lk + 3][lr] = wR.w;
            if (lr < BM) {
                sA[nb][lk + 0][lr] = aR.x; sA[nb][lk + 1][lr] = aR.y;
                sA[nb][lk + 2][lr] = aR.z; sA[nb][lk + 3][lr] = aR.w;
            }
            __syncthreads();
        }
    }

#pragma unroll
    for (int i = 0; i < TM; i++) {
        int gr = bm + ty * TM + i;
        if (gr >= M) continue;
        int id = 0;
        if (EPI == 2) {
            if (IM == 1)      id = idxA[gr];
            else if (IM == 2) id = (gr < E) ? idxA[gr] : idxB[gr - E];
            else              id = (gr < E) ? idxA[gr] : (gr - E);
        }
#pragma unroll
        for (int j = 0; j < 4; j++) {
            int gc = bn + tx * 4 + j;
            if (gc >= Nc) continue;
            float v = acc[i][j];
            if (EPI == 1)      v += bias[gc];
            else if (EPI == 2) v = fmaxf(v + addMat[(size_t)id * addStride + gc], 0.f);
            C[(size_t)gr * ldc + gc] = v;
        }
    }
}

// ---------------- step 0: sum_h = gated = 0 exactly -> elementwise ---------
__global__ void k_step0(const int* __restrict__ word_ids, float* __restrict__ hout) {
    int n = blockIdx.x, c = threadIdx.x;
    int wid = word_ids[n];
    const float* e = g_Epre + (size_t)wid * 1024;
    float z  = 1.f / (1.f + expf(-e[c]));
    float ht = tanhf(e[512 + c]);
    hout[n * H + c] = z * ht;
}

// ---------------- per-step gather (h_nei only, pad rows skipped) -----------
__global__ void k_gather(int t, const int* __restrict__ word_ids,
                         const int* __restrict__ h_nei) {
    __shared__ int s_hi[NB], s_wid;
    int n = blockIdx.x, j = threadIdx.x;
    int base = t * NN + n;
    if (j < NB) s_hi[j] = h_nei[base * NB + j];
    if (j == 0) s_wid = word_ids[base];
    __syncthreads();
    float rx = g_Epre[(size_t)s_wid * 1024 + 256 + j];
    float sh = 0.f, g = 0.f;
#pragma unroll
    for (int nb = 0; nb < NB; nb++) {
        int hi = s_hi[nb];
        if (hi == E) continue;   // warp-uniform branch; bit-exact skip
        float v  = g_hbuf[(size_t)hi * H + j];
        float rp = g_Urh[(size_t)hi * H + j];
        sh += v;
        g  += v / (1.f + expf(-(rx + rp)));
    }
    g_sh[n * H + j] = sh;
    g_xg[n * H + j] = g;
}

// ---------------- fused z/h GEMM + GRU combine (16-row tiles, 256 CTAs) ----
__global__ void __launch_bounds__(256) k_gemmZH(
    const float* __restrict__ Wzh, const float* __restrict__ Whh,  // h-halves, ldw 512
    const int* __restrict__ wid_t, float* __restrict__ hout) {
    const int bm = blockIdx.y * 16, bn = blockIdx.x * 64;
    __shared__ __align__(16) float sA1[2][16][16], sA2[2][16][16];
    __shared__ __align__(16) float sW1[2][16][64], sW2[2][16][64];
    const int tid = threadIdx.x;
    const int tx = tid & 15, ty = tid >> 4;   // 1 row, 4 cols per thread
    float accZ[4] = {0.f, 0.f, 0.f, 0.f}, accH[4] = {0.f, 0.f, 0.f, 0.f};
    const int lr = tid >> 2, lk = (tid & 3) << 2;
    const int half = tid >> 7, lar = (tid & 127) >> 2;   // lar 0..31, valid <16
    const bool aload = lar < 16;
    const float* Wzp = Wzh + (size_t)(bn + lr) * 512 + lk;
    const float* Whp = Whh + (size_t)(bn + lr) * 512 + lk;
    const float* Ap = (half ? g_xg : g_sh) + (size_t)(bm + (aload ? lar : 0)) * H + lk;

    float4 w1R = *(const float4*)(Wzp);
    float4 w2R = *(const float4*)(Whp);
    float4 aR  = aload ? *(const float4*)(Ap) : make_float4(0.f, 0.f, 0.f, 0.f);
    sW1[0][lk + 0][lr] = w1R.x; sW1[0][lk + 1][lr] = w1R.y;
    sW1[0][lk + 2][lr] = w1R.z; sW1[0][lk + 3][lr] = w1R.w;
    sW2[0][lk + 0][lr] = w2R.x; sW2[0][lk + 1][lr] = w2R.y;
    sW2[0][lk + 2][lr] = w2R.z; sW2[0][lk + 3][lr] = w2R.w;
    if (aload) {
        float (*dA)[16][16] = half ? sA2 : sA1;
        dA[0][lk + 0][lar] = aR.x; dA[0][lk + 1][lar] = aR.y;
        dA[0][lk + 2][lar] = aR.z; dA[0][lk + 3][lar] = aR.w;
    }
    __syncthreads();

    for (int p = 0; p < 16; p++) {
        const int cb = p & 1, nb = cb ^ 1;
        if (p < 15) {
            int k0 = (p + 1) * 16;
            w1R = *(const float4*)(Wzp + k0);
            w2R = *(const float4*)(Whp + k0);
            if (aload) aR = *(const float4*)(Ap + k0);
        }
#pragma unroll
        for (int k = 0; k < 16; k++) {
            float a1 = sA1[cb][k][ty];
            float a2 = sA2[cb][k][ty];
            float4 wz = *(const float4*)&sW1[cb][k][tx * 4];
            float4 wh = *(const float4*)&sW2[cb][k][tx * 4];
            accZ[0] += a1 * wz.x; accZ[1] += a1 * wz.y;
            accZ[2] += a1 * wz.z; accZ[3] += a1 * wz.w;
            accH[0] += a2 * wh.x; accH[1] += a2 * wh.y;
            accH[2] += a2 * wh.z; accH[3] += a2 * wh.w;
        }
        if (p < 15) {
            sW1[nb][lk + 0][lr] = w1R.x; sW1[nb][lk + 1][lr] = w1R.y;
            sW1[nb][lk + 2][lr] = w1R.z; sW1[nb][lk + 3][lr] = w1R.w;
            sW2[nb][lk + 0][lr] = w2R.x; sW2[nb][lk + 1][lr] = w2R.y;
            sW2[nb][lk + 2][lr] = w2R.z; sW2[nb][lk + 3][lr] = w2R.w;
            if (aload) {
                float (*dA)[16][16] = half ? sA2 : sA1;
                dA[nb][lk + 0][lar] = aR.x; dA[nb][lk + 1][lar] = aR.y;
                dA[nb][lk + 2][lar] = aR.z; dA[nb][lk + 3][lar] = aR.w;
            }
            __syncthreads();
        }
    }

    const int r0 = bm + ty;
    int w0 = wid_t[r0];
    const float* e0 = g_Epre + (size_t)w0 * 1024;
    float o0[4];
#pragma unroll
    for (int j = 0; j < 4; j++) {
        int c = bn + tx * 4 + j;
        float z0 = 1.f / (1.f + expf(-(accZ[j] + e0[c])));
        float t0 = tanhf(accH[j] + e0[512 + c]);
        o0[j] = (1.f - z0) * g_sh[(size_t)r0 * H + c] + z0 * t0;
    }
    *(float4*)&hout[(size_t)r0 * H + bn + tx * 4] = make_float4(o0[0], o0[1], o0[2], o0[3]);
}

// ---------------- post-loop: cur_o for all edges (pad rows skipped) --------
__global__ void k_curo(const int* __restrict__ o_nei) {
    __shared__ int s_oi[NB];
    int e = blockIdx.x, j = threadIdx.x;
    if (j < NB) s_oi[j] = o_nei[e * NB + j];
    __syncthreads();
    float co = 0.f;
#pragma unroll
    for (int nb = 0; nb < NB; nb++) {
        int oi = s_oi[nb];
        if (oi == E) continue;
        co += g_hbuf[(size_t)oi * H + j];
    }
    g_curo[(size_t)e * H + j] = co;
}

// ---------------- stop-head root rows (pad rows skipped) ----------------
__global__ void k_stopRoot(const int* __restrict__ root_o_idx) {
    __shared__ int s_oi[NB];
    int b = blockIdx.x, j = threadIdx.x;
    if (j < NB) s_oi[j] = root_o_idx[b * NB + j];
    __syncthreads();
    float s = 0.f;
#pragma unroll
    for (int nb = 0; nb < NB; nb++) {
        int oi = s_oi[nb];
        if (oi == E) continue;
        s += g_hbuf[(size_t)oi * H + j];
    }
    g_curo[(size_t)(E + b) * H + j] = s;
}

// ---------------- compact pred rows ----------------
__global__ void k_compact(const int* __restrict__ direction, const int* __restrict__ contexts) {
    __shared__ int warpsum[32];
    __shared__ int sbase;
    int tid = threadIdx.x, lane = tid & 31, w = tid >> 5;
    if (tid == 0) sbase = 0;
    __syncthreads();
    for (int chunk = 0; chunk < R; chunk += 1024) {
        int i = chunk + tid;
        int m = 0;
        if (i < R) m = (i < BB) ? 1 : (direction[i - BB] != 0);
        unsigned bal = __ballot_sync(0xffffffffu, m);
        int pre = __popc(bal & ((1u << lane) - 1u));
        if (lane == 0) warpsum[w] = __popc(bal);
        __syncthreads();
        if (tid < 32) {
            int v = warpsum[tid];
#pragma unroll
            for (int off = 1; off < 32; off <<= 1) {
                int o = __shfl_up_sync(0xffffffffu, v, off);
                if (tid >= off) v += o;
            }
            warpsum[tid] = v;
        }
        __syncthreads();
        int wbase = (w == 0) ? 0 : warpsum[w - 1];
        if (m) {
            int pos = sbase + wbase + pre;
            g_pidx[pos] = i;
            g_pctx[pos] = (i < BB) ? i : contexts[i - BB];
        }
        __syncthreads();
        if (tid == 0) sbase += warpsum[31];
        __syncthreads();
    }
    if (tid == 0) g_cnt = sbase;
}

// ---------------- pred row reduction ----------------
__global__ void k_predReduce(const int* __restrict__ pred_targets,
                             const int* __restrict__ root_word_ids) {
    int w = threadIdx.x >> 5, lane = threadIdx.x & 31;
    int r = blockIdx.x * 8 + w;
    if (r >= g_cnt) return;
    int gi = g_pidx[r];
    const float* row = g_big + (size_t)r * V;
    float bv = -INFINITY; int bi = 0x7fffffff;
    for (int j = lane; j < V; j += 32) {
        float v = row[j];
        if (v > bv) { bv = v; bi = j; }
    }
#pragma unroll
    for (int off = 16; off; off >>= 1) {
        float ov = __shfl_xor_sync(0xffffffffu, bv, off);
        int   oi = __shfl_xor_sync(0xffffffffu, bi, off);
        if (ov > bv || (ov == bv && oi < bi)) { bv = ov; bi = oi; }
    }
    float s = 0.f;
    for (int j = lane; j < V; j += 32) s += expf(row[j] - bv);
#pragma unroll
    for (int off = 16; off; off >>= 1) s += __shfl_xor_sync(0xffffffffu, s, off);
    if (lane == 0) {
        int tgt = (gi < BB) ? root_word_ids[gi] : pred_targets[gi - BB];
        g_rowNll[r] = bv + logf(s) - row[tgt];
        g_rowHit[r] = (bi == tgt) ? 1.f : 0.f;
    }
}

// ---------------- stop scalar dot + bce ----------------
__global__ void k_stopDot(const float* __restrict__ Uo_w, const float* __restrict__ Uo_b,
                          const int* __restrict__ direction) {
    int w = threadIdx.x >> 5, lane = threadIdx.x & 31;
    int gi = blockIdx.x * 8 + w;
    if (gi >= R) return;
    const float* row = g_big + (size_t)gi * H;
    float s = 0.f;
#pragma unroll
    for (int k = lane; k < H; k += 32) s += row[k] * Uo_w[k];
#pragma unroll
    for (int off = 16; off; off >>= 1) s += __shfl_xor_sync(0xffffffffu, s, off);
    if (lane == 0) {
        s += Uo_b[0];
        float tgt = (gi < E) ? (float)direction[gi] : 0.f;
        g_rowBce[gi] = fmaxf(s, 0.f) - s * tgt + log1pf(expf(-fabsf(s)));
        float pred = (s >= 0.f) ? 1.f : 0.f;
        g_rowSAcc[gi] = (pred == tgt) ? 1.f : 0.f;
    }
}

// ---------------- final reduction ----------------
__global__ void k_final(float* __restrict__ out) {
    __shared__ float sm[1024];
    int tid = threadIdx.x;
    int cnt = g_cnt;
    float a0 = 0.f, a1 = 0.f, a3 = 0.f, a4 = 0.f;
    for (int i = tid; i < cnt; i += 1024) { a0 += g_rowNll[i]; a1 += g_rowHit[i]; }
    for (int i = tid; i < R; i += 1024)   { a3 += g_rowBce[i]; a4 += g_rowSAcc[i]; }
    auto red = [&](float v) -> float {
        sm[tid] = v; __syncthreads();
        for (int s = 512; s; s >>= 1) { if (tid < s) sm[tid] += sm[tid + s]; __syncthreads(); }
        float r = sm[0]; __syncthreads();
        return r;
    };
    float nll = red(a0), hit = red(a1), bce = red(a3), sac = red(a4);
    if (tid == 0) {
        out[0] = nll / (float)BB;
        out[1] = bce / (float)BB;
        out[2] = hit / (float)cnt;
        out[3] = sac / (float)R;
    }
}

// ---------------- launch ----------------
extern "C" void kernel_launch(void* const* d_in, const int* in_sizes, int n_in,
                              void* d_out, int out_size) {
    const float* emb    = (const float*)d_in[0];
    const float* W_z_w  = (const float*)d_in[1];
    const float* W_z_b  = (const float*)d_in[2];
    const float* W_r_w  = (const float*)d_in[3];
    const float* W_r_b  = (const float*)d_in[4];
    const float* U_r_w  = (const float*)d_in[5];
    const float* W_h_w  = (const float*)d_in[6];
    const float* W_h_b  = (const float*)d_in[7];
    const float* W_w    = (const float*)d_in[8];
    const float* W_b    = (const float*)d_in[9];
    const float* Wo_w   = (const float*)d_in[10];
    const float* Wo_b   = (const float*)d_in[11];
    const float* U_w    = (const float*)d_in[12];
    const float* U_b    = (const float*)d_in[13];
    const float* Ui_w   = (const float*)d_in[14];
    const float* Ui_b   = (const float*)d_in[15];
    const float* Uo_w   = (const float*)d_in[16];
    const float* Uo_b   = (const float*)d_in[17];
    const float* xtree  = (const float*)d_in[18];
    const int* word_ids = (const int*)d_in[19];
    const int* h_nei    = (const int*)d_in[20];
    const int* o_nei    = (const int*)d_in[21];
    const int* contexts = (const int*)d_in[22];
    const int* pred_t   = (const int*)d_in[23];
    const int* directn  = (const int*)d_in[24];
    const int* root_wid = (const int*)d_in[25];
    const int* root_oid = (const int*)d_in[26];
    float* out = (float*)d_out;

    float *p_hbuf, *p_Urh, *p_Epre, *p_Xpu, *p_Wcat, *p_Wx, *p_bcat, *p_bcat2,
          *p_h2, *p_big, *p_curo;
    int *p_cnt, *p_pctx, *p_pidx;
    cudaGetSymbolAddress((void**)&p_hbuf, g_hbuf);
    cudaGetSymbolAddress((void**)&p_Urh, g_Urh);
    cudaGetSymbolAddress((void**)&p_Epre, g_Epre);
    cudaGetSymbolAddress((void**)&p_Xpu, g_Xpu);
    cudaGetSymbolAddress((void**)&p_Wcat, g_Wcat);
    cudaGetSymbolAddress((void**)&p_Wx, g_Wx);
    cudaGetSymbolAddress((void**)&p_bcat, g_bcat);
    cudaGetSymbolAddress((void**)&p_bcat2, g_bcat2);
    cudaGetSymbolAddress((void**)&p_h2, g_h2);
    cudaGetSymbolAddress((void**)&p_big, g_big);
    cudaGetSymbolAddress((void**)&p_curo, g_curo);
    cudaGetSymbolAddress((void**)&p_cnt, g_cnt);
    cudaGetSymbolAddress((void**)&p_pctx, g_pctx);
    cudaGetSymbolAddress((void**)&p_pidx, g_pidx);

    // ---- one-time precomputes ----
    k_init<<<2, 256>>>();
    k_prep<<<1536, 256>>>(W_z_w, W_z_b, W_r_w, W_r_b, W_h_w, W_h_b, Ui_w, Ui_b,
                          W_w, W_b, U_w, U_b);
    // Epre = emb @ Wcat^T + bcat    (800 x 1024)
    k_gemm<64, 1, 0, false><<<dim3(16, 13), 256>>>(emb, H, 800, nullptr, p_Wcat, H, 1024, H,
                                                   p_bcat, p_Epre, 1024, nullptr, 0,
                                                   nullptr, nullptr, nullptr);
    // Xpu = xtree @ Wx^T + bcat2    (256 x 512)
    k_gemm<64, 1, 0, false><<<dim3(8, 4), 256>>>(xtree, LDIM, BB, nullptr, p_Wx, LDIM, 512, LDIM,
                                                 p_bcat2, p_Xpu, 512, nullptr, 0,
                                                 nullptr, nullptr, nullptr);

    // ---- recurrent loop ----
    // t = 0: all h_nei hit the zero pad row -> newh = sig(E_z)*tanh(E_h) exactly
    k_step0<<<NN, 256>>>(word_ids, p_hbuf);
    k_gemm<16, 0, 0, false><<<dim3(4, 64), 256>>>(p_hbuf, H, NN, nullptr,
                                                  U_r_w, H, H, H, nullptr,
                                                  p_Urh, H, nullptr, 0,
                                                  nullptr, nullptr, nullptr);
    for (int t = 1; t < T_STEPS; t++) {
        k_gather<<<NN, 256>>>(t, word_ids, h_nei);
        k_gemmZH<<<dim3(4, 64), 256>>>(W_z_w + 256, W_h_w + 256, word_ids + t * NN,
                                       p_hbuf + (size_t)t * NN * H);
        if (t < T_STEPS - 1)   // Urh(31) is never read
            k_gemm<16, 0, 0, false><<<dim3(4, 64), 256>>>(p_hbuf + (size_t)t * NN * H, H, NN, nullptr,
                                                          U_r_w, H, H, H, nullptr,
                                                          p_Urh + (size_t)t * NN * H, H, nullptr, 0,
                                                          nullptr, nullptr, nullptr);
    }

    // ---- cur_o for all edges (off the serial path) ----
    k_curo<<<E, 256>>>(o_nei);

    // ---- word prediction head (mask-compacted, gathered A) ----
    k_compact<<<1, 1024>>>(directn, contexts);
    k_gemm<64, 2, 1, true><<<dim3(4, 516), 256>>>(nullptr, H, R, p_cnt, W_w, 384, H, H,
                                                  nullptr, p_h2, H, p_Xpu, 512,
                                                  p_pctx, nullptr, p_pidx);
    k_gemm<64, 1, 0, false><<<dim3(13, 516), 256>>>(p_h2, H, R, p_cnt, Wo_w, H, V, H,
                                                    Wo_b, p_big, V, nullptr, 0,
                                                    nullptr, nullptr, nullptr);
    k_predReduce<<<(R + 7) / 8, 256>>>(pred_t, root_wid);

    // ---- stop head ----
    k_stopRoot<<<BB, 256>>>(root_oid);
    k_gemm<64, 2, 2, false><<<dim3(4, 516), 256>>>(p_curo, H, R, nullptr, Ui_w + 256, 512, H, H,
                                                   nullptr, p_h2, H, p_Epre + 768, 1024,
                                                   word_ids, root_wid, nullptr);
    k_gemm<64, 2, 3, false><<<dim3(4, 516), 256>>>(p_h2, H, R, nullptr, U_w, 384, H, H,
                                                   nullptr, p_big, H, p_Xpu + 256, 512,
                                                   contexts, nullptr, nullptr);
    k_stopDot<<<(R + 7) / 8, 256>>>(Uo_w, Uo_b, directn);

    k_final<<<1, 1024>>>(out);
}

// round 17
// speedup vs baseline: 1.3210x; 1.3210x over previous
#include <cuda_runtime.h>
#include <math.h>

#define T_STEPS 32
#define NN      1024
#define H       256
#define LDIM    128
#define V       800
#define BB      256
#define NB      15
#define E       (T_STEPS * NN)   /* 32768 */
#define R       (E + BB)         /* 33024 */

// ---------------- device scratch ----------------
__device__ float g_hbuf[(E + 1) * H];
__device__ float g_Urh[(E + 1) * H];
__device__ float g_curo[(size_t)R * H];
__device__ float g_sh[NN * H];
__device__ float g_xg[NN * H];
__device__ float g_Epre[800 * 1024];   // [E_z|E_r|E_h|E_ui] per word, biases folded
__device__ float g_Xpu[BB * 512];      // [Xp|Xu] per context, biases folded
__device__ float g_Wcat[1024 * H];
__device__ float g_Wx[512 * LDIM];
__device__ float g_bcat[1024];
__device__ float g_bcat2[512];
__device__ float g_h2[(size_t)R * H];
__device__ float g_big[(size_t)R * V];
__device__ int   g_pidx[R];
__device__ int   g_pctx[R];
__device__ int   g_cnt;
__device__ float g_rowNll[R], g_rowHit[R], g_rowBce[R], g_rowSAcc[R];

// ---------------- init ----------------
__global__ void k_init() {
    int j = threadIdx.x;
    if (blockIdx.x == 0) g_hbuf[E * H + j] = 0.f;
    else                 g_Urh[E * H + j] = 0.f;
}

// ---------------- build combined weights ----------------
__global__ void k_prep(const float* __restrict__ Wz, const float* __restrict__ Wzb,
                       const float* __restrict__ Wr, const float* __restrict__ Wrb,
                       const float* __restrict__ Wh, const float* __restrict__ Whb,
                       const float* __restrict__ Ui, const float* __restrict__ Uib,
                       const float* __restrict__ Ww, const float* __restrict__ Wb,
                       const float* __restrict__ Uw, const float* __restrict__ Ub) {
    int r = blockIdx.x, j = threadIdx.x;
    if (r < 1024) {
        int rr = r & 255;
        float v, b;
        if (r < 256)      { v = Wz[rr * 512 + j]; b = Wzb[rr]; }
        else if (r < 512) { v = Wr[rr * 256 + j]; b = Wrb[rr]; }
        else if (r < 768) { v = Wh[rr * 512 + j]; b = Whb[rr]; }
        else              { v = Ui[rr * 512 + j]; b = Uib[rr]; }
        g_Wcat[r * H + j] = v;
        if (j == 0) g_bcat[r] = b;
    } else {
        int r2 = r - 1024;
        int rr = r2 & 255;
        if (j < LDIM)
            g_Wx[r2 * LDIM + j] = (r2 < 256) ? Ww[rr * 384 + 256 + j] : Uw[rr * 384 + 256 + j];
        if (j == 0) g_bcat2[r2] = (r2 < 256) ? Wb[rr] : Ub[rr];
    }
}

// ---------------- double-buffered fp32 GEMM: C = epi(A[M,K] @ W[Nc,K]^T) ---
// EPI: 0=plain 1=+bias 2=relu(+addMat[id])
// IM (EPI==2): 1 id=idxA[gr]; 2 id=gr<E?idxA[gr]:idxB[gr-E]; 3 id=gr<E?idxA[gr]:gr-E
// GA: A rows gathered from g_hbuf via gidx (pi<BB -> zero row)
template <int BM, int EPI, int IM, bool GA>
__global__ void __launch_bounds__(256) k_gemm(
    const float* __restrict__ A, int lda, int Mh, const int* __restrict__ Mptr,
    const float* __restrict__ W, int ldw, int Nc, int K,
    const float* __restrict__ bias,
    float* __restrict__ C, int ldc,
    const float* __restrict__ addMat, int addStride,
    const int* __restrict__ idxA, const int* __restrict__ idxB,
    const int* __restrict__ gidx) {
    const int M = Mptr ? *Mptr : Mh;
    const int bm = blockIdx.y * BM;
    if (bm >= M) return;
    const int bn = blockIdx.x * 64;
    __shared__ __align__(16) float sA[2][16][BM];
    __shared__ __align__(16) float sW[2][16][64];
    const int tid = threadIdx.x;
    constexpr int TM = BM / 16;
    const int tx = tid & 15, ty = tid >> 4;
    float acc[TM][4];
#pragma unroll
    for (int i = 0; i < TM; i++)
#pragma unroll
        for (int j = 0; j < 4; j++) acc[i][j] = 0.f;
    const int lr = tid >> 2, lk = (tid & 3) << 2;
    const bool wok = (bn + lr) < Nc;
    bool aok = (lr < BM) && ((bm + lr) < M);
    const float* Wp = W + (size_t)(bn + lr) * ldw + lk;
    const float* Ap = A;
    if (GA) {
        Ap = g_hbuf;
        if (aok) {
            int pi = gidx[bm + lr];
            if (pi < BB) aok = false;
            else Ap = g_hbuf + (size_t)(pi - BB) * H + lk;
        }
    } else {
        Ap = A + (size_t)(bm + (lr < BM ? lr : 0)) * lda + lk;
    }

    const int P = K / 16;
    const float4 z4 = make_float4(0.f, 0.f, 0.f, 0.f);
    float4 wR = wok ? *(const float4*)(Wp) : z4;
    float4 aR = z4;
    if (lr < BM) aR = aok ? *(const float4*)(Ap) : z4;
    sW[0][lk + 0][lr] = wR.x; sW[0][lk + 1][lr] = wR.y;
    sW[0][lk + 2][lr] = wR.z; sW[0][lk + 3][lr] = wR.w;
    if (lr < BM) {
        sA[0][lk + 0][lr] = aR.x; sA[0][lk + 1][lr] = aR.y;
        sA[0][lk + 2][lr] = aR.z; sA[0][lk + 3][lr] = aR.w;
    }
    __syncthreads();

    for (int p = 0; p < P; p++) {
        const int cb = p & 1, nb = cb ^ 1;
        if (p + 1 < P) {
            int k0 = (p + 1) * 16;
            wR = wok ? *(const float4*)(Wp + k0) : z4;
            if (lr < BM) aR = aok ? *(const float4*)(Ap + k0) : z4;
        }
#pragma unroll
        for (int k = 0; k < 16; k++) {
            float4 wv = *(const float4*)&sW[cb][k][tx * 4];
            if constexpr (TM == 4) {
                float4 av = *(const float4*)&sA[cb][k][ty * 4];
                acc[0][0] += av.x * wv.x; acc[0][1] += av.x * wv.y; acc[0][2] += av.x * wv.z; acc[0][3] += av.x * wv.w;
                acc[1][0] += av.y * wv.x; acc[1][1] += av.y * wv.y; acc[1][2] += av.y * wv.z; acc[1][3] += av.y * wv.w;
                acc[2][0] += av.z * wv.x; acc[2][1] += av.z * wv.y; acc[2][2] += av.z * wv.z; acc[2][3] += av.z * wv.w;
                acc[3][0] += av.w * wv.x; acc[3][1] += av.w * wv.y; acc[3][2] += av.w * wv.z; acc[3][3] += av.w * wv.w;
            } else {
                float2 av = *(const float2*)&sA[cb][k][ty * 2];
                acc[0][0] += av.x * wv.x; acc[0][1] += av.x * wv.y; acc[0][2] += av.x * wv.z; acc[0][3] += av.x * wv.w;
                acc[1][0] += av.y * wv.x; acc[1][1] += av.y * wv.y; acc[1][2] += av.y * wv.z; acc[1][3] += av.y * wv.w;
            }
        }
        if (p + 1 < P) {
            sW[nb][lk + 0][lr] = wR.x; sW[nb][lk + 1][lr] = wR.y;
            sW[nb][lk + 2][lr] = wR.z; sW[nb][lk + 3][lr] = wR.w;
            if (lr < BM) {
                sA[nb][lk + 0][lr] = aR.x; sA[nb][lk + 1][lr] = aR.y;
                sA[nb][lk + 2][lr] = aR.z; sA[nb][lk + 3][lr] = aR.w;
            }
            __syncthreads();
        }
    }

#pragma unroll
    for (int i = 0; i < TM; i++) {
        int gr = bm + ty * TM + i;
        if (gr >= M) continue;
        int id = 0;
        if (EPI == 2) {
            if (IM == 1)      id = idxA[gr];
            else if (IM == 2) id = (gr < E) ? idxA[gr] : idxB[gr - E];
            else              id = (gr < E) ? idxA[gr] : (gr - E);
        }
#pragma unroll
        for (int j = 0; j < 4; j++) {
            int gc = bn + tx * 4 + j;
            if (gc >= Nc) continue;
            float v = acc[i][j];
            if (EPI == 1)      v += bias[gc];
            else if (EPI == 2) v = fmaxf(v + addMat[(size_t)id * addStride + gc], 0.f);
            C[(size_t)gr * ldc + gc] = v;
        }
    }
}

// ---------------- step 0: sum_h = gated = 0 exactly -> elementwise ---------
__global__ void k_step0(const int* __restrict__ word_ids, float* __restrict__ hout) {
    int n = blockIdx.x, c = threadIdx.x;
    int wid = word_ids[n];
    const float* e = g_Epre + (size_t)wid * 1024;
    float z  = 1.f / (1.f + expf(-e[c]));
    float ht = tanhf(e[512 + c]);
    hout[n * H + c] = z * ht;
}

// ---------------- per-step gather (h_nei only, pad rows skipped) -----------
// Pad index E points at the all-zero row: contributes exactly +0.0f -> skip.
__global__ void k_gather(int t, const int* __restrict__ word_ids,
                         const int* __restrict__ h_nei) {
    __shared__ int s_hi[NB], s_wid;
    int n = blockIdx.x, j = threadIdx.x;
    int base = t * NN + n;
    if (j < NB) s_hi[j] = h_nei[base * NB + j];
    if (j == 0) s_wid = word_ids[base];
    __syncthreads();
    float rx = g_Epre[(size_t)s_wid * 1024 + 256 + j];
    float sh = 0.f, g = 0.f;
#pragma unroll
    for (int nb = 0; nb < NB; nb++) {
        int hi = s_hi[nb];
        if (hi == E) continue;   // warp-uniform branch; bit-exact skip
        float v  = g_hbuf[(size_t)hi * H + j];
        float rp = g_Urh[(size_t)hi * H + j];
        sh += v;
        g  += v / (1.f + expf(-(rx + rp)));
    }
    g_sh[n * H + j] = sh;
    g_xg[n * H + j] = g;
}

// ---------------- fused z/h GEMM + GRU combine (double-buffered) -----------
__global__ void __launch_bounds__(256) k_gemmZH(
    const float* __restrict__ Wzh, const float* __restrict__ Whh,  // h-halves, ldw 512
    const int* __restrict__ wid_t, float* __restrict__ hout) {
    const int bm = blockIdx.y * 32, bn = blockIdx.x * 64;
    __shared__ __align__(16) float sA1[2][16][32], sA2[2][16][32];
    __shared__ __align__(16) float sW1[2][16][64], sW2[2][16][64];
    const int tid = threadIdx.x;
    const int tx = tid & 15, ty = tid >> 4;
    float accZ[2][4], accH[2][4];
#pragma unroll
    for (int i = 0; i < 2; i++)
#pragma unroll
        for (int j = 0; j < 4; j++) { accZ[i][j] = 0.f; accH[i][j] = 0.f; }
    const int lr = tid >> 2, lk = (tid & 3) << 2;
    const int half = tid >> 7, lar = (tid & 127) >> 2;
    const float* Wzp = Wzh + (size_t)(bn + lr) * 512 + lk;
    const float* Whp = Whh + (size_t)(bn + lr) * 512 + lk;
    const float* Ap = (half ? g_xg : g_sh) + (size_t)(bm + lar) * H + lk;

    float4 w1R = *(const float4*)(Wzp);
    float4 w2R = *(const float4*)(Whp);
    float4 aR  = *(const float4*)(Ap);
    sW1[0][lk + 0][lr] = w1R.x; sW1[0][lk + 1][lr] = w1R.y;
    sW1[0][lk + 2][lr] = w1R.z; sW1[0][lk + 3][lr] = w1R.w;
    sW2[0][lk + 0][lr] = w2R.x; sW2[0][lk + 1][lr] = w2R.y;
    sW2[0][lk + 2][lr] = w2R.z; sW2[0][lk + 3][lr] = w2R.w;
    if (half) {
        sA2[0][lk + 0][lar] = aR.x; sA2[0][lk + 1][lar] = aR.y;
        sA2[0][lk + 2][lar] = aR.z; sA2[0][lk + 3][lar] = aR.w;
    } else {
        sA1[0][lk + 0][lar] = aR.x; sA1[0][lk + 1][lar] = aR.y;
        sA1[0][lk + 2][lar] = aR.z; sA1[0][lk + 3][lar] = aR.w;
    }
    __syncthreads();

    for (int p = 0; p < 16; p++) {
        const int cb = p & 1, nb = cb ^ 1;
        if (p < 15) {
            int k0 = (p + 1) * 16;
            w1R = *(const float4*)(Wzp + k0);
            w2R = *(const float4*)(Whp + k0);
            aR  = *(const float4*)(Ap + k0);
        }
#pragma unroll
        for (int k = 0; k < 16; k++) {
            float2 a1v = *(const float2*)&sA1[cb][k][ty * 2];
            float2 a2v = *(const float2*)&sA2[cb][k][ty * 2];
            float4 wz = *(const float4*)&sW1[cb][k][tx * 4];
            float4 wh = *(const float4*)&sW2[cb][k][tx * 4];
            accZ[0][0] += a1v.x * wz.x; accZ[0][1] += a1v.x * wz.y;
            accZ[0][2] += a1v.x * wz.z; accZ[0][3] += a1v.x * wz.w;
            accZ[1][0] += a1v.y * wz.x; accZ[1][1] += a1v.y * wz.y;
            accZ[1][2] += a1v.y * wz.z; accZ[1][3] += a1v.y * wz.w;
            accH[0][0] += a2v.x * wh.x; accH[0][1] += a2v.x * wh.y;
            accH[0][2] += a2v.x * wh.z; accH[0][3] += a2v.x * wh.w;
            accH[1][0] += a2v.y * wh.x; accH[1][1] += a2v.y * wh.y;
            accH[1][2] += a2v.y * wh.z; accH[1][3] += a2v.y * wh.w;
        }
        if (p < 15) {
            sW1[nb][lk + 0][lr] = w1R.x; sW1[nb][lk + 1][lr] = w1R.y;
            sW1[nb][lk + 2][lr] = w1R.z; sW1[nb][lk + 3][lr] = w1R.w;
            sW2[nb][lk + 0][lr] = w2R.x; sW2[nb][lk + 1][lr] = w2R.y;
            sW2[nb][lk + 2][lr] = w2R.z; sW2[nb][lk + 3][lr] = w2R.w;
            if (half) {
                sA2[nb][lk + 0][lar] = aR.x; sA2[nb][lk + 1][lar] = aR.y;
                sA2[nb][lk + 2][lar] = aR.z; sA2[nb][lk + 3][lar] = aR.w;
            } else {
                sA1[nb][lk + 0][lar] = aR.x; sA1[nb][lk + 1][lar] = aR.y;
                sA1[nb][lk + 2][lar] = aR.z; sA1[nb][lk + 3][lar] = aR.w;
            }
            __syncthreads();
        }
    }

    const int r0 = bm + ty * 2;
    int w0 = wid_t[r0], w1 = wid_t[r0 + 1];
    const float* e0 = g_Epre + (size_t)w0 * 1024;
    const float* e1 = g_Epre + (size_t)w1 * 1024;
    float o0[4], o1[4];
#pragma unroll
    for (int j = 0; j < 4; j++) {
        int c = bn + tx * 4 + j;
        float z0 = 1.f / (1.f + expf(-(accZ[0][j] + e0[c])));
        float z1 = 1.f / (1.f + expf(-(accZ[1][j] + e1[c])));
        float t0 = tanhf(accH[0][j] + e0[512 + c]);
        float t1 = tanhf(accH[1][j] + e1[512 + c]);
        o0[j] = (1.f - z0) * g_sh[(size_t)r0 * H + c] + z0 * t0;
        o1[j] = (1.f - z1) * g_sh[(size_t)(r0 + 1) * H + c] + z1 * t1;
    }
    *(float4*)&hout[(size_t)r0 * H + bn + tx * 4]       = make_float4(o0[0], o0[1], o0[2], o0[3]);
    *(float4*)&hout[(size_t)(r0 + 1) * H + bn + tx * 4] = make_float4(o1[0], o1[1], o1[2], o1[3]);
}

// ------ cur_o for all edges + root rows, one launch (pad rows skipped) -----
__global__ void k_curoAll(const int* __restrict__ o_nei, const int* __restrict__ root_o_idx) {
    __shared__ int s_oi[NB];
    int e = blockIdx.x, j = threadIdx.x;
    const int* src = (e < E) ? (o_nei + e * NB) : (root_o_idx + (e - E) * NB);
    if (j < NB) s_oi[j] = src[j];
    __syncthreads();
    float co = 0.f;
#pragma unroll
    for (int nb = 0; nb < NB; nb++) {
        int oi = s_oi[nb];
        if (oi == E) continue;   // zero row: +0.0f exactly
        co += g_hbuf[(size_t)oi * H + j];
    }
    g_curo[(size_t)e * H + j] = co;
}

// ---------------- compact pred rows ----------------
__global__ void k_compact(const int* __restrict__ direction, const int* __restrict__ contexts) {
    __shared__ int warpsum[32];
    __shared__ int sbase;
    int tid = threadIdx.x, lane = tid & 31, w = tid >> 5;
    if (tid == 0) sbase = 0;
    __syncthreads();
    for (int chunk = 0; chunk < R; chunk += 1024) {
        int i = chunk + tid;
        int m = 0;
        if (i < R) m = (i < BB) ? 1 : (direction[i - BB] != 0);
        unsigned bal = __ballot_sync(0xffffffffu, m);
        int pre = __popc(bal & ((1u << lane) - 1u));
        if (lane == 0) warpsum[w] = __popc(bal);
        __syncthreads();
        if (tid < 32) {
            int v = warpsum[tid];
#pragma unroll
            for (int off = 1; off < 32; off <<= 1) {
                int o = __shfl_up_sync(0xffffffffu, v, off);
                if (tid >= off) v += o;
            }
            warpsum[tid] = v;
        }
        __syncthreads();
        int wbase = (w == 0) ? 0 : warpsum[w - 1];
        if (m) {
            int pos = sbase + wbase + pre;
            g_pidx[pos] = i;
            g_pctx[pos] = (i < BB) ? i : contexts[i - BB];
        }
        __syncthreads();
        if (tid == 0) sbase += warpsum[31];
        __syncthreads();
    }
    if (tid == 0) g_cnt = sbase;
}

// ---------------- pred row reduction ----------------
__global__ void k_predReduce(const int* __restrict__ pred_targets,
                             const int* __restrict__ root_word_ids) {
    int w = threadIdx.x >> 5, lane = threadIdx.x & 31;
    int r = blockIdx.x * 8 + w;
    if (r >= g_cnt) return;
    int gi = g_pidx[r];
    const float* row = g_big + (size_t)r * V;
    float bv = -INFINITY; int bi = 0x7fffffff;
    for (int j = lane; j < V; j += 32) {
        float v = row[j];
        if (v > bv) { bv = v; bi = j; }
    }
#pragma unroll
    for (int off = 16; off; off >>= 1) {
        float ov = __shfl_xor_sync(0xffffffffu, bv, off);
        int   oi = __shfl_xor_sync(0xffffffffu, bi, off);
        if (ov > bv || (ov == bv && oi < bi)) { bv = ov; bi = oi; }
    }
    float s = 0.f;
    for (int j = lane; j < V; j += 32) s += expf(row[j] - bv);
#pragma unroll
    for (int off = 16; off; off >>= 1) s += __shfl_xor_sync(0xffffffffu, s, off);
    if (lane == 0) {
        int tgt = (gi < BB) ? root_word_ids[gi] : pred_targets[gi - BB];
        g_rowNll[r] = bv + logf(s) - row[tgt];
        g_rowHit[r] = (bi == tgt) ? 1.f : 0.f;
    }
}

// ---------------- stop scalar dot + bce ----------------
__global__ void k_stopDot(const float* __restrict__ Uo_w, const float* __restrict__ Uo_b,
                          const int* __restrict__ direction) {
    int w = threadIdx.x >> 5, lane = threadIdx.x & 31;
    int gi = blockIdx.x * 8 + w;
    if (gi >= R) return;
    const float* row = g_big + (size_t)gi * H;
    float s = 0.f;
#pragma unroll
    for (int k = lane; k < H; k += 32) s += row[k] * Uo_w[k];
#pragma unroll
    for (int off = 16; off; off >>= 1) s += __shfl_xor_sync(0xffffffffu, s, off);
    if (lane == 0) {
        s += Uo_b[0];
        float tgt = (gi < E) ? (float)direction[gi] : 0.f;
        g_rowBce[gi] = fmaxf(s, 0.f) - s * tgt + log1pf(expf(-fabsf(s)));
        float pred = (s >= 0.f) ? 1.f : 0.f;
        g_rowSAcc[gi] = (pred == tgt) ? 1.f : 0.f;
    }
}

// ---------------- final reduction ----------------
__global__ void k_final(float* __restrict__ out) {
    __shared__ float sm[1024];
    int tid = threadIdx.x;
    int cnt = g_cnt;
    float a0 = 0.f, a1 = 0.f, a3 = 0.f, a4 = 0.f;
    for (int i = tid; i < cnt; i += 1024) { a0 += g_rowNll[i]; a1 += g_rowHit[i]; }
    for (int i = tid; i < R; i += 1024)   { a3 += g_rowBce[i]; a4 += g_rowSAcc[i]; }
    auto red = [&](float v) -> float {
        sm[tid] = v; __syncthreads();
        for (int s = 512; s; s >>= 1) { if (tid < s) sm[tid] += sm[tid + s]; __syncthreads(); }
        float r = sm[0]; __syncthreads();
        return r;
    };
    float nll = red(a0), hit = red(a1), bce = red(a3), sac = red(a4);
    if (tid == 0) {
        out[0] = nll / (float)BB;
        out[1] = bce / (float)BB;
        out[2] = hit / (float)cnt;
        out[3] = sac / (float)R;
    }
}

// ---------------- launch ----------------
extern "C" void kernel_launch(void* const* d_in, const int* in_sizes, int n_in,
                              void* d_out, int out_size) {
    const float* emb    = (const float*)d_in[0];
    const float* W_z_w  = (const float*)d_in[1];
    const float* W_z_b  = (const float*)d_in[2];
    const float* W_r_w  = (const float*)d_in[3];
    const float* W_r_b  = (const float*)d_in[4];
    const float* U_r_w  = (const float*)d_in[5];
    const float* W_h_w  = (const float*)d_in[6];
    const float* W_h_b  = (const float*)d_in[7];
    const float* W_w    = (const float*)d_in[8];
    const float* W_b    = (const float*)d_in[9];
    const float* Wo_w   = (const float*)d_in[10];
    const float* Wo_b   = (const float*)d_in[11];
    const float* U_w    = (const float*)d_in[12];
    const float* U_b    = (const float*)d_in[13];
    const float* Ui_w   = (const float*)d_in[14];
    const float* Ui_b   = (const float*)d_in[15];
    const float* Uo_w   = (const float*)d_in[16];
    const float* Uo_b   = (const float*)d_in[17];
    const float* xtree  = (const float*)d_in[18];
    const int* word_ids = (const int*)d_in[19];
    const int* h_nei    = (const int*)d_in[20];
    const int* o_nei    = (const int*)d_in[21];
    const int* contexts = (const int*)d_in[22];
    const int* pred_t   = (const int*)d_in[23];
    const int* directn  = (const int*)d_in[24];
    const int* root_wid = (const int*)d_in[25];
    const int* root_oid = (const int*)d_in[26];
    float* out = (float*)d_out;

    float *p_hbuf, *p_Urh, *p_Epre, *p_Xpu, *p_Wcat, *p_Wx, *p_bcat, *p_bcat2,
          *p_h2, *p_big, *p_curo;
    int *p_cnt, *p_pctx, *p_pidx;
    cudaGetSymbolAddress((void**)&p_hbuf, g_hbuf);
    cudaGetSymbolAddress((void**)&p_Urh, g_Urh);
    cudaGetSymbolAddress((void**)&p_Epre, g_Epre);
    cudaGetSymbolAddress((void**)&p_Xpu, g_Xpu);
    cudaGetSymbolAddress((void**)&p_Wcat, g_Wcat);
    cudaGetSymbolAddress((void**)&p_Wx, g_Wx);
    cudaGetSymbolAddress((void**)&p_bcat, g_bcat);
    cudaGetSymbolAddress((void**)&p_bcat2, g_bcat2);
    cudaGetSymbolAddress((void**)&p_h2, g_h2);
    cudaGetSymbolAddress((void**)&p_big, g_big);
    cudaGetSymbolAddress((void**)&p_curo, g_curo);
    cudaGetSymbolAddress((void**)&p_cnt, g_cnt);
    cudaGetSymbolAddress((void**)&p_pctx, g_pctx);
    cudaGetSymbolAddress((void**)&p_pidx, g_pidx);

    // ---- one-time precomputes ----
    k_init<<<2, 256>>>();
    k_prep<<<1536, 256>>>(W_z_w, W_z_b, W_r_w, W_r_b, W_h_w, W_h_b, Ui_w, Ui_b,
                          W_w, W_b, U_w, U_b);
    // Epre = emb @ Wcat^T + bcat    (800 x 1024)
    k_gemm<64, 1, 0, false><<<dim3(16, 13), 256>>>(emb, H, 800, nullptr, p_Wcat, H, 1024, H,
                                                   p_bcat, p_Epre, 1024, nullptr, 0,
                                                   nullptr, nullptr, nullptr);
    // Xpu = xtree @ Wx^T + bcat2    (256 x 512)
    k_gemm<64, 1, 0, false><<<dim3(8, 4), 256>>>(xtree, LDIM, BB, nullptr, p_Wx, LDIM, 512, LDIM,
                                                 p_bcat2, p_Xpu, 512, nullptr, 0,
                                                 nullptr, nullptr, nullptr);
    // compact depends only on direction/contexts -> off the critical chain here
    k_compact<<<1, 1024>>>(directn, contexts);

    // ---- recurrent loop ----
    // t = 0: all h_nei hit the zero pad row -> newh = sig(E_z)*tanh(E_h) exactly
    k_step0<<<NN, 256>>>(word_ids, p_hbuf);
    k_gemm<32, 0, 0, false><<<dim3(4, 32), 256>>>(p_hbuf, H, NN, nullptr,
                                                  U_r_w, H, H, H, nullptr,
                                                  p_Urh, H, nullptr, 0,
                                                  nullptr, nullptr, nullptr);
    for (int t = 1; t < T_STEPS; t++) {
        k_gather<<<NN, 256>>>(t, word_ids, h_nei);
        k_gemmZH<<<dim3(4, 32), 256>>>(W_z_w + 256, W_h_w + 256, word_ids + t * NN,
                                       p_hbuf + (size_t)t * NN * H);
        if (t < T_STEPS - 1)   // Urh(31) is never read
            k_gemm<32, 0, 0, false><<<dim3(4, 32), 256>>>(p_hbuf + (size_t)t * NN * H, H, NN, nullptr,
                                                          U_r_w, H, H, H, nullptr,
                                                          p_Urh + (size_t)t * NN * H, H, nullptr, 0,
                                                          nullptr, nullptr, nullptr);
    }

    // ---- cur_o for all edges + roots, one launch (off the serial path) ----
    k_curoAll<<<E + BB, 256>>>(o_nei, root_oid);

    // ---- word prediction head (mask-compacted, gathered A) ----
    k_gemm<64, 2, 1, true><<<dim3(4, 516), 256>>>(nullptr, H, R, p_cnt, W_w, 384, H, H,
                                                  nullptr, p_h2, H, p_Xpu, 512,
                                                  p_pctx, nullptr, p_pidx);
    k_gemm<64, 1, 0, false><<<dim3(13, 516), 256>>>(p_h2, H, R, p_cnt, Wo_w, H, V, H,
                                                    Wo_b, p_big, V, nullptr, 0,
                                                    nullptr, nullptr, nullptr);
    k_predReduce<<<(R + 7) / 8, 256>>>(pred_t, root_wid);

    // ---- stop head ----
    k_gemm<64, 2, 2, false><<<dim3(4, 516), 256>>>(p_curo, H, R, nullptr, Ui_w + 256, 512, H, H,
                                                   nullptr, p_h2, H, p_Epre + 768, 1024,
                                                   word_ids, root_wid, nullptr);
    k_gemm<64, 2, 3, false><<<dim3(4, 516), 256>>>(p_h2, H, R, nullptr, U_w, 384, H, H,
                                                   nullptr, p_big, H, p_Xpu + 256, 512,
                                                   contexts, nullptr, nullptr);
    k_stopDot<<<(R + 7) / 8, 256>>>(Uo_w, Uo_b, directn);

    k_final<<<1, 1024>>>(out);
}